// round 15
// baseline (speedup 1.0000x reference)
#include <cuda_runtime.h>
#include <stdint.h>

#define Kb     256
#define Dd     128
#define Ff     1025
#define NROWS  1024
#define CSTR   (512*1025)
#define MW     96
#define NFP    1056
#define NPAIR  528

typedef unsigned long long ull;

// ---- static device scratch ----
__device__ int   g_fmin2[NPAIR], g_wid2[NPAIR];
__device__ float g_M[(size_t)NPAIR*MW*32];   // [pair][j][s(2)][c(4)][c2(4)]
__device__ float g_bias[NFP*4];

__device__ __forceinline__ ull splat2(float v) {
    ull r; asm("mov.b64 %0, {%1, %1};" : "=l"(r) : "f"(v)); return r;
}
__device__ __forceinline__ void ffma2(ull& d, ull a, ull b) {
    asm("fma.rn.f32x2 %0, %1, %2, %0;" : "+l"(d) : "l"(a), "l"(b));
}
__device__ __forceinline__ void unpack2(ull v, float& lo, float& hi) {
    asm("mov.b64 {%0, %1}, %2;" : "=f"(lo), "=f"(hi) : "l"(v));
}

// ---------------------------------------------------------------------------
// k_buildM: one block per f'. Builds banded M and bias DIRECTLY from W1/W2
// (no Weff intermediate): per (j,c,c2), M = inv_ola(f) * sum_d mel_d[w] *
// dot128(W1[k_d][4w+c][:], W2[k_d][:,4w'_d+c2]).
// Also computes band stats + pair windows in-kernel (warp-ballot scans).
// ---------------------------------------------------------------------------
__global__ __launch_bounds__(256) void k_buildM(
    const float* __restrict__ W1, const float* __restrict__ b1,
    const float* __restrict__ W2, const float* __restrict__ b2,
    const int*   __restrict__ nzidx, const float* __restrict__ nzmel,
    const float* __restrict__ mask,  const float* __restrict__ ola, int Wb)
{
    const int f   = blockIdx.x;
    const int KeW = 4*Wb;
    const int p   = f >> 1;
    const int s   = f & 1;
    const int tid = threadIdx.x;
    const int wrp = tid >> 5, lane = tid & 31;

    __shared__ int s_flo[Kb], s_nz[Kb];
    __shared__ int s_k[4], s_flo4[4], s_nz4[4], s_wp[4];
    __shared__ int s_info[3];                              // deg, fm2, wid
    __shared__ __align__(16) float W2sT[4][4][132];        // [band][c2][dd] padded (132f = 33x16B)
    __shared__ __align__(16) float s_mel[4][64];
    __shared__ float s_scl;

    // --- per-band stats: warp per band, coalesced mask scan + ballot count
    for (int k = wrp; k < Kb; k += 8) {
        int n = 0;
        for (int w0 = 0; w0 < Wb; w0 += 32) {
            int w = w0 + lane;
            bool m = (w < Wb) && (mask[k*Wb + w] > 0.5f);
            n += __popc(__ballot_sync(0xffffffffu, m));
        }
        if (lane == 0) { s_nz[k] = n; s_flo[k] = nzidx[k*Wb]; }
    }
    if (tid == 0) s_scl = (f < Ff) ? (1.0f / ola[f]) : 0.0f;
    __syncthreads();

    // --- band scan for this f (and pair-union window over {f, f^1})
    if (tid < 32) {
        const int fo = f ^ 1;
        int fmn = 1<<29, fmx = -1;
        int deg = 0;
        for (int w = 0; w < 8; ++w) {
            int k   = w*32 + tid;
            int flo = s_flo[k], nz = s_nz[k];
            bool cs = (f  < Ff) && (f  >= flo) && (f  < flo + nz);
            bool co = (fo < Ff) && (fo >= flo) && (fo < flo + nz);
            if (cs | co) { fmn = min(fmn, flo); fmx = max(fmx, flo + nz); }
            unsigned bs = __ballot_sync(0xffffffffu, cs);
            if (tid == 0) {
                while (bs) {
                    int b = __ffs(bs) - 1; bs &= bs - 1;
                    if (deg < 4) {
                        int kk = w*32 + b;
                        s_k[deg]    = kk;
                        s_flo4[deg] = s_flo[kk];
                        s_nz4[deg]  = s_nz[kk];
                        s_wp[deg]   = f - s_flo[kk];
                        ++deg;
                    }
                }
            }
        }
        #pragma unroll
        for (int off = 16; off; off >>= 1) {
            fmn = min(fmn, __shfl_xor_sync(0xffffffffu, fmn, off));
            fmx = max(fmx, __shfl_xor_sync(0xffffffffu, fmx, off));
        }
        if (tid == 0) {
            for (int d = deg; d < 4; ++d) { s_k[d]=0; s_flo4[d]=1<<29; s_nz4[d]=0; s_wp[d]=0; }
            int fm2, wid;
            if (fmx < 0) { fm2 = 0; wid = 0; }
            else         { fm2 = fmn; wid = min(fmx - fmn, MW); }
            g_fmin2[p] = fm2;       // pair members write identical values
            g_wid2[p]  = wid;
            s_info[0] = deg; s_info[1] = fm2; s_info[2] = wid;
        }
    }
    __syncthreads();

    const int deg = s_info[0], fm2 = s_info[1], wid = s_info[2];

    // --- stage W2 column slices (transposed, padded) + mel vectors
    for (int d = 0; d < deg; ++d) {
        if (tid < Dd) {
            float4 v = *reinterpret_cast<const float4*>(
                W2 + ((size_t)s_k[d]*Dd + tid)*KeW + 4*s_wp[d]);
            W2sT[d][0][tid] = v.x;
            W2sT[d][1][tid] = v.y;
            W2sT[d][2][tid] = v.z;
            W2sT[d][3][tid] = v.w;
        } else {
            int w = tid - 128;
            if (w < s_nz4[d] && w < 64)
                s_mel[d][w] = nzmel[s_k[d]*Wb + w];
        }
    }
    __syncthreads();

    const float scl = s_scl;

    // --- main: each thread computes elements of M[f][j][c][c2]
    for (int pos = tid; pos < wid*16; pos += 256) {
        int j  = pos >> 4;
        int c  = (pos >> 2) & 3;
        int c2 = pos & 3;
        int fbin = fm2 + j;
        float acc = 0.0f;
        #pragma unroll
        for (int d = 0; d < 4; ++d) {
            int w = fbin - s_flo4[d];
            bool valid = (d < deg) && (w >= 0) && (w < s_nz4[d]);
            if (valid) {
                const float4* a = reinterpret_cast<const float4*>(
                    W1 + ((size_t)s_k[d]*KeW + 4*w + c)*Dd);
                const float* bcol = &W2sT[d][c2][0];
                float dot = 0.0f;
                #pragma unroll 8
                for (int q = 0; q < 32; ++q) {
                    float4 av = a[q];
                    float4 bv = *reinterpret_cast<const float4*>(&bcol[q*4]);
                    dot += av.x*bv.x; dot += av.y*bv.y;
                    dot += av.z*bv.z; dot += av.w*bv.w;
                }
                acc += s_mel[d][w] * dot;
            }
        }
        g_M[(((size_t)p*MW + j)*2 + s)*16 + c*4 + c2] = acc * scl;
    }

    // --- bias
    if (tid < 4) {
        float v = 0.0f;
        for (int d = 0; d < deg; ++d) {
            float dot = 0.0f;
            const float* b1p = b1 + s_k[d]*Dd;
            const float* wc  = &W2sT[d][tid][0];
            for (int dd = 0; dd < Dd; ++dd) dot += b1p[dd] * wc[dd];
            v += dot + b2[(size_t)s_k[d]*KeW + 4*s_wp[d] + tid];
        }
        g_bias[f*4 + tid] = v * scl;
    }
}

// ---------------------------------------------------------------------------
// k_main: block = 64 rows x 16 f'; warp = 1 f'-pair; lane = 1 row-pair.
// (R8/R13 configuration — best measured.) bmin/bwid reduced in-kernel.
// ---------------------------------------------------------------------------
__global__ __launch_bounds__(256, 2) void k_main(
    const float* __restrict__ x, float* __restrict__ out, int sstr)
{
    extern __shared__ __align__(16) float smx[];   // [32 rowpairs][sstr floats]
    float* smo = smx;                              // aliases (x dead at epilogue)
    __shared__ int sbm[2];

    const int tid   = threadIdx.x;
    const int wrp   = tid >> 5, lane = tid & 31;
    const int f0    = blockIdx.x * 16;
    const int p0    = f0 >> 1;
    const int row0  = blockIdx.y * 64;

    if (tid < 8) {
        int pq = p0 + tid;
        int wq = g_wid2[pq];
        int mn = wq > 0 ? g_fmin2[pq]      : (1<<29);
        int mx = wq > 0 ? g_fmin2[pq] + wq : -1;
        #pragma unroll
        for (int off = 4; off; off >>= 1) {
            mn = min(mn, __shfl_xor_sync(0xffu, mn, off));
            mx = max(mx, __shfl_xor_sync(0xffu, mx, off));
        }
        if (tid == 0) {
            sbm[0] = (mx < 0) ? 0 : mn;
            sbm[1] = (mx < 0) ? 0 : (mx - mn);
        }
    }
    __syncthreads();
    const int bmin = sbm[0];
    const int bwid = sbm[1];

    // staging: warp wrp stages rowpairs 4*wrp..4*wrp+3; lanes stride bins.
    #pragma unroll
    for (int q = 0; q < 4; ++q) {
        const int rp  = wrp*4 + q;
        const int rowE = row0 + 2*rp, rowO = rowE + 1;
        const int bE = rowE >> 9, tE = rowE & 511;
        const int bO = rowO >> 9, tO = rowO & 511;
        const float* xe = x + ((size_t)(bE*4)*512 + tE)*Ff + bmin;
        const float* xo = x + ((size_t)(bO*4)*512 + tO)*Ff + bmin;
        float* dst = smx + rp*sstr;
        for (int u = lane; u < bwid; u += 32) {
            float4 ve = make_float4(xe[u], xe[u+CSTR], xe[u+(size_t)2*CSTR], xe[u+(size_t)3*CSTR]);
            float4 vo = make_float4(xo[u], xo[u+CSTR], xo[u+(size_t)2*CSTR], xo[u+(size_t)3*CSTR]);
            *reinterpret_cast<float4*>(dst + u*8)     = ve;
            *reinterpret_cast<float4*>(dst + u*8 + 4) = vo;
        }
    }
    __syncthreads();

    const int p    = p0 + wrp;
    const int jmax = g_wid2[p];
    const int u0   = g_fmin2[p] - bmin;
    const int fA   = 2*p;

    const ulonglong2* mbase = reinterpret_cast<const ulonglong2*>(g_M + (size_t)p*MW*32);
    ulonglong2 bAv = *reinterpret_cast<const ulonglong2*>(&g_bias[fA*4]);
    ulonglong2 bBv = *reinterpret_cast<const ulonglong2*>(&g_bias[fA*4 + 4]);

    ull aE00 = bAv.x, aE01 = bAv.y, aE10 = bBv.x, aE11 = bBv.y;
    ull aO00 = bAv.x, aO01 = bAv.y, aO10 = bBv.x, aO11 = bBv.y;

    const float* xp = smx + lane*sstr + u0*8;

    #pragma unroll 2
    for (int j = 0; j < jmax; ++j) {
        const ulonglong2* m = mbase + j*8;
        ulonglong2 m0 = m[0], m1 = m[1], m2 = m[2], m3 = m[3];
        ulonglong2 m4 = m[4], m5 = m[5], m6 = m[6], m7 = m[7];
        const float* xj = xp + j*8;
        float4 Xe = *reinterpret_cast<const float4*>(xj);
        float4 Xo = *reinterpret_cast<const float4*>(xj + 4);
        ull s;
        s = splat2(Xe.x);
        ffma2(aE00, s, m0.x); ffma2(aE01, s, m0.y);
        ffma2(aE10, s, m4.x); ffma2(aE11, s, m4.y);
        s = splat2(Xe.y);
        ffma2(aE00, s, m1.x); ffma2(aE01, s, m1.y);
        ffma2(aE10, s, m5.x); ffma2(aE11, s, m5.y);
        s = splat2(Xe.z);
        ffma2(aE00, s, m2.x); ffma2(aE01, s, m2.y);
        ffma2(aE10, s, m6.x); ffma2(aE11, s, m6.y);
        s = splat2(Xe.w);
        ffma2(aE00, s, m3.x); ffma2(aE01, s, m3.y);
        ffma2(aE10, s, m7.x); ffma2(aE11, s, m7.y);
        s = splat2(Xo.x);
        ffma2(aO00, s, m0.x); ffma2(aO01, s, m0.y);
        ffma2(aO10, s, m4.x); ffma2(aO11, s, m4.y);
        s = splat2(Xo.y);
        ffma2(aO00, s, m1.x); ffma2(aO01, s, m1.y);
        ffma2(aO10, s, m5.x); ffma2(aO11, s, m5.y);
        s = splat2(Xo.z);
        ffma2(aO00, s, m2.x); ffma2(aO01, s, m2.y);
        ffma2(aO10, s, m6.x); ffma2(aO11, s, m6.y);
        s = splat2(Xo.w);
        ffma2(aO00, s, m3.x); ffma2(aO01, s, m3.y);
        ffma2(aO10, s, m7.x); ffma2(aO11, s, m7.y);
    }

    __syncthreads();   // x tile dead; smo aliases smx

    // stage results: smo[row(64)][c2(4)*17 + fx(16)]
    {
        int rowl = 2*lane;
        float v0,v1,v2,v3;
        #pragma unroll
        for (int g = 0; g < 2; ++g) {
            int fx = 2*wrp + g;
            ull a0 = g ? aE10 : aE00, a1 = g ? aE11 : aE01;
            unpack2(a0, v0, v1); unpack2(a1, v2, v3);
            smo[rowl*69 + 0*17 + fx] = v0;
            smo[rowl*69 + 1*17 + fx] = v1;
            smo[rowl*69 + 2*17 + fx] = v2;
            smo[rowl*69 + 3*17 + fx] = v3;
            ull b0 = g ? aO10 : aO00, b1 = g ? aO11 : aO01;
            unpack2(b0, v0, v1); unpack2(b1, v2, v3);
            smo[(rowl+1)*69 + 0*17 + fx] = v0;
            smo[(rowl+1)*69 + 1*17 + fx] = v1;
            smo[(rowl+1)*69 + 2*17 + fx] = v2;
            smo[(rowl+1)*69 + 3*17 + fx] = v3;
        }
    }
    __syncthreads();

    // coalesced store: warp wrp covers rows 8*wrp..8*wrp+7
    #pragma unroll
    for (int rr = 0; rr < 8; ++rr) {
        const int r   = wrp*8 + rr;
        const int row = row0 + r, b = row >> 9, t = row & 511;
        #pragma unroll
        for (int h = 0; h < 2; ++h) {
            int e   = h*32 + lane;          // 0..63
            int fx  = e & 15, cc2 = e >> 4;
            int f = f0 + fx;
            if (f < Ff)
                out[((size_t)(b*4 + cc2)*512 + t)*Ff + f] = smo[r*69 + cc2*17 + fx];
        }
    }
}

// ---------------------------------------------------------------------------
extern "C" void kernel_launch(void* const* d_in, const int* in_sizes, int n_in,
                              void* d_out, int out_size)
{
    const float* x     = (const float*)d_in[0];
    const float* W1    = (const float*)d_in[1];
    const float* b1    = (const float*)d_in[2];
    const float* W2    = (const float*)d_in[3];
    const float* b2    = (const float*)d_in[4];
    const int*   nzidx = (const int*)  d_in[5];
    const float* nzmel = (const float*)d_in[6];
    const float* mask  = (const float*)d_in[7];
    const float* ola   = (const float*)d_in[8];

    const int Wb = in_sizes[5] / Kb;

    k_buildM<<<NFP, 256>>>(W1, b1, W2, b2, nzidx, nzmel, mask, ola, Wb);

    int xrange = 2*Wb + 16;
    int sstr = 8*xrange + 4;                     // floats per rowpair
    int main_smem = 32 * sstr * (int)sizeof(float);
    int smo_need = 64*69*(int)sizeof(float);
    if (main_smem < smo_need) main_smem = smo_need;
    cudaFuncSetAttribute(k_main, cudaFuncAttributeMaxDynamicSharedMemorySize, main_smem);
    k_main<<<dim3((Ff + 15)/16, NROWS/64), 256, main_smem>>>(x, (float*)d_out, sstr);
}

// round 17
// speedup vs baseline: 1.3922x; 1.3922x over previous
#include <cuda_runtime.h>
#include <stdint.h>

#define Kb     256
#define Dd     128
#define KEMAX  256
#define Ff     1025
#define NROWS  1024
#define CSTR   (512*1025)
#define MW     96
#define NFP    1056
#define NPAIR  528

typedef unsigned long long ull;

// ---- static device scratch ----
__device__ float g_Weff[(size_t)Kb*KEMAX*KEMAX];
__device__ float g_beff[Kb*KEMAX];
__device__ int   g_flo[Kb], g_nz[Kb];
__device__ int   g_fmin2[NPAIR], g_wid2[NPAIR];
__device__ float g_M[(size_t)NPAIR*MW*32];   // [pair][j][s(2)][c(4)][c2(4)]
__device__ float g_bias[NFP*4];

__device__ __forceinline__ ull splat2(float v) {
    ull r; asm("mov.b64 %0, {%1, %1};" : "=l"(r) : "f"(v)); return r;
}
__device__ __forceinline__ void ffma2(ull& d, ull a, ull b) {
    asm("fma.rn.f32x2 %0, %1, %2, %0;" : "+l"(d) : "l"(a), "l"(b));
}
__device__ __forceinline__ void unpack2(ull v, float& lo, float& hi) {
    asm("mov.b64 {%0, %1}, %2;" : "=f"(lo), "=f"(hi) : "l"(v));
}

// ---------------------------------------------------------------------------
// k_weff: per-band fused W1@W2 (mel, 1/ola folded). grid (Kb, itiles of 16).
// Self-sufficient: computes its band's nnz/flo; y==0 publishes g_nz/g_flo.
// d-loop unrolled 8 for MLP against L2 latency on W2.
// ---------------------------------------------------------------------------
__global__ __launch_bounds__(256) void k_weff(
    const float* __restrict__ W1, const float* __restrict__ b1,
    const float* __restrict__ W2, const float* __restrict__ b2,
    const int*   __restrict__ nzidx, const float* __restrict__ nzmel,
    const float* __restrict__ mask,  const float* __restrict__ ola, int Wb)
{
    __shared__ float W1s[16*Dd];
    __shared__ float cs[KEMAX];
    __shared__ float rs[16];
    __shared__ float b1s[Dd];
    __shared__ int s_nnz;

    const int k     = blockIdx.x;
    const int KeW   = 4*Wb;
    const int iBase = blockIdx.y * 16;
    const int tid   = threadIdx.x;

    if (tid == 0) {
        int n = 0;
        for (int w = 0; w < Wb; ++w) n += (mask[k*Wb + w] > 0.5f);
        s_nnz = n;
        if (blockIdx.y == 0) { g_nz[k] = n; g_flo[k] = nzidx[k*Wb]; }
    }
    __syncthreads();

    const int nnz = s_nnz;
    const int Ke4 = 4*nnz;
    if (iBase >= Ke4) return;
    const int ni = min(16, Ke4 - iBase);

    for (int j = tid; j < ni*Dd; j += 256)
        W1s[j] = W1[((size_t)k*KeW + iBase)*Dd + j];
    for (int w = tid; w < nnz; w += 256) {
        float inv = 1.0f / ola[nzidx[k*Wb + w]];
        cs[4*w+0]=inv; cs[4*w+1]=inv; cs[4*w+2]=inv; cs[4*w+3]=inv;
    }
    if (tid < ni) rs[tid] = nzmel[k*Wb + ((iBase + tid) >> 2)];
    if (tid < Dd) b1s[tid] = b1[k*Dd + tid];
    __syncthreads();

    const int nct = Ke4 >> 2, nrt = ni >> 2;
    if (tid < nrt*nct) {
        const int tr = tid / nct, tc = tid - tr*nct;
        ull acc[4][2] = {{0,0},{0,0},{0,0},{0,0}};
        const float* a = &W1s[(tr*4)*Dd];
        const float* w2base = W2 + (size_t)k*Dd*KeW + tc*4;
        #pragma unroll 8
        for (int d = 0; d < Dd; ++d) {
            ulonglong2 bv = *reinterpret_cast<const ulonglong2*>(w2base + (size_t)d*KeW);
            ull s;
            s = splat2(a[d]);      ffma2(acc[0][0], s, bv.x); ffma2(acc[0][1], s, bv.y);
            s = splat2(a[Dd+d]);   ffma2(acc[1][0], s, bv.x); ffma2(acc[1][1], s, bv.y);
            s = splat2(a[2*Dd+d]); ffma2(acc[2][0], s, bv.x); ffma2(acc[2][1], s, bv.y);
            s = splat2(a[3*Dd+d]); ffma2(acc[3][0], s, bv.x); ffma2(acc[3][1], s, bv.y);
        }
        const int gi = iBase + tr*4, go = tc*4;
        float4 c4 = *reinterpret_cast<const float4*>(&cs[go]);
        #pragma unroll
        for (int rr = 0; rr < 4; ++rr) {
            float v0,v1,v2,v3;
            unpack2(acc[rr][0], v0, v1);
            unpack2(acc[rr][1], v2, v3);
            float r = rs[tr*4+rr];
            float4 o4 = make_float4(v0*r*c4.x, v1*r*c4.y, v2*r*c4.z, v3*r*c4.w);
            *reinterpret_cast<float4*>(&g_Weff[((size_t)k*KeW + gi+rr)*KeW + go]) = o4;
        }
    }

    if (blockIdx.y == 0) {
        for (int o = tid; o < Ke4; o += 256) {
            float s = b2[(size_t)k*KeW + o];
            #pragma unroll 8
            for (int d = 0; d < Dd; ++d) s += b1s[d] * W2[((size_t)k*Dd + d)*KeW + o];
            g_beff[k*KEMAX + o] = s * cs[o];
        }
    }
}

// ---------------------------------------------------------------------------
// k_scatter: fused band-scan (ballot over 256 bands, deterministic order)
// + banded-M assembly in pair-interleaved layout
//   g_M[((p*MW + j)*2 + s)*16 + c*4 + c2],  s = f&1
// ---------------------------------------------------------------------------
__global__ __launch_bounds__(256) void k_scatter(int Wb)
{
    const int f   = blockIdx.x;
    const int KeW = 4*Wb;
    const int p   = f >> 1;
    const int s   = f & 1;
    const int tid = threadIdx.x;

    __shared__ int s_flo[Kb], s_nz[Kb];
    __shared__ int s_k[4], s_flo4[4], s_nz4[4], s_wp[4];
    __shared__ int s_info[3];   // deg, fm2, wid

    s_flo[tid] = g_flo[tid];
    s_nz[tid]  = g_nz[tid];
    __syncthreads();

    if (tid < 32) {
        const int fo = f ^ 1;
        int fmn = 1<<29, fmx = -1;
        int deg = 0;
        for (int w = 0; w < 8; ++w) {
            int k   = w*32 + tid;
            int flo = s_flo[k], nz = s_nz[k];
            bool cs = (f  < Ff) && (f  >= flo) && (f  < flo + nz);
            bool co = (fo < Ff) && (fo >= flo) && (fo < flo + nz);
            if (cs | co) { fmn = min(fmn, flo); fmx = max(fmx, flo + nz); }
            unsigned bs = __ballot_sync(0xffffffffu, cs);
            if (tid == 0) {
                while (bs) {
                    int b = __ffs(bs) - 1; bs &= bs - 1;
                    if (deg < 4) {
                        int kk = w*32 + b;
                        s_k[deg]    = kk;
                        s_flo4[deg] = s_flo[kk];
                        s_nz4[deg]  = s_nz[kk];
                        s_wp[deg]   = f - s_flo[kk];
                        ++deg;
                    }
                }
            }
        }
        #pragma unroll
        for (int off = 16; off; off >>= 1) {
            fmn = min(fmn, __shfl_xor_sync(0xffffffffu, fmn, off));
            fmx = max(fmx, __shfl_xor_sync(0xffffffffu, fmx, off));
        }
        if (tid == 0) {
            for (int d = deg; d < 4; ++d) { s_k[d]=0; s_flo4[d]=1<<29; s_nz4[d]=0; s_wp[d]=0; }
            int fm2, wid;
            if (fmx < 0) { fm2 = 0; wid = 0; }
            else         { fm2 = fmn; wid = min(fmx - fmn, MW); }
            g_fmin2[p] = fm2;
            g_wid2[p]  = wid;
            s_info[0] = deg; s_info[1] = fm2; s_info[2] = wid;
        }
    }
    __syncthreads();

    const int deg = s_info[0], fm2 = s_info[1], wid = s_info[2];

    for (int pos = tid; pos < wid*4; pos += 256) {
        int j = pos >> 2;
        int c = pos & 3;
        int fbin = fm2 + j;
        float4 u[4];
        #pragma unroll
        for (int d = 0; d < 4; ++d) {
            int w = fbin - s_flo4[d];
            bool pv = (d < deg) && (w >= 0) && (w < s_nz4[d]);
            u[d] = pv ? *reinterpret_cast<const float4*>(
                     &g_Weff[((size_t)s_k[d]*KeW + 4*w + c)*KeW + 4*s_wp[d]])
                      : make_float4(0.f,0.f,0.f,0.f);
        }
        float4 v;
        v.x = (u[0].x + u[1].x) + (u[2].x + u[3].x);
        v.y = (u[0].y + u[1].y) + (u[2].y + u[3].y);
        v.z = (u[0].z + u[1].z) + (u[2].z + u[3].z);
        v.w = (u[0].w + u[1].w) + (u[2].w + u[3].w);
        *reinterpret_cast<float4*>(
            &g_M[(((size_t)p*MW + j)*2 + s)*16 + c*4]) = v;
    }
    if (tid < 4) {
        float v = 0.0f;
        for (int d = 0; d < deg; ++d)
            v += g_beff[s_k[d]*KEMAX + 4*s_wp[d] + tid];
        g_bias[f*4 + tid] = v;
    }
}

// ---------------------------------------------------------------------------
// k_main: block = 64 rows x 16 f'; warp = 1 f'-pair; lane = 1 row-pair.
// x staged with __ldcs (streaming, evict-first) so L1 retains the M slices.
// ---------------------------------------------------------------------------
__global__ __launch_bounds__(256, 2) void k_main(
    const float* __restrict__ x, float* __restrict__ out, int sstr)
{
    extern __shared__ __align__(16) float smx[];   // [32 rowpairs][sstr floats]
    float* smo = smx;                              // aliases (x dead at epilogue)
    __shared__ int sbm[2];

    const int tid   = threadIdx.x;
    const int wrp   = tid >> 5, lane = tid & 31;
    const int f0    = blockIdx.x * 16;
    const int p0    = f0 >> 1;
    const int row0  = blockIdx.y * 64;

    if (tid < 8) {
        int pq = p0 + tid;
        int wq = g_wid2[pq];
        int mn = wq > 0 ? g_fmin2[pq]      : (1<<29);
        int mx = wq > 0 ? g_fmin2[pq] + wq : -1;
        #pragma unroll
        for (int off = 4; off; off >>= 1) {
            mn = min(mn, __shfl_xor_sync(0xffu, mn, off));
            mx = max(mx, __shfl_xor_sync(0xffu, mx, off));
        }
        if (tid == 0) {
            sbm[0] = (mx < 0) ? 0 : mn;
            sbm[1] = (mx < 0) ? 0 : (mx - mn);
        }
    }
    __syncthreads();
    const int bmin = sbm[0];
    const int bwid = sbm[1];

    // staging: warp wrp stages rowpairs 4*wrp..4*wrp+3; lanes stride bins.
    // __ldcs: streaming loads (evict-first) keep L1 resident for g_M.
    #pragma unroll
    for (int q = 0; q < 4; ++q) {
        const int rp  = wrp*4 + q;
        const int rowE = row0 + 2*rp, rowO = rowE + 1;
        const int bE = rowE >> 9, tE = rowE & 511;
        const int bO = rowO >> 9, tO = rowO & 511;
        const float* xe = x + ((size_t)(bE*4)*512 + tE)*Ff + bmin;
        const float* xo = x + ((size_t)(bO*4)*512 + tO)*Ff + bmin;
        float* dst = smx + rp*sstr;
        for (int u = lane; u < bwid; u += 32) {
            float4 ve = make_float4(__ldcs(xe+u), __ldcs(xe+u+CSTR),
                                    __ldcs(xe+u+(size_t)2*CSTR), __ldcs(xe+u+(size_t)3*CSTR));
            float4 vo = make_float4(__ldcs(xo+u), __ldcs(xo+u+CSTR),
                                    __ldcs(xo+u+(size_t)2*CSTR), __ldcs(xo+u+(size_t)3*CSTR));
            *reinterpret_cast<float4*>(dst + u*8)     = ve;
            *reinterpret_cast<float4*>(dst + u*8 + 4) = vo;
        }
    }
    __syncthreads();

    const int p    = p0 + wrp;
    const int jmax = g_wid2[p];
    const int u0   = g_fmin2[p] - bmin;
    const int fA   = 2*p;

    const ulonglong2* mbase = reinterpret_cast<const ulonglong2*>(g_M + (size_t)p*MW*32);
    ulonglong2 bAv = *reinterpret_cast<const ulonglong2*>(&g_bias[fA*4]);
    ulonglong2 bBv = *reinterpret_cast<const ulonglong2*>(&g_bias[fA*4 + 4]);

    ull aE00 = bAv.x, aE01 = bAv.y, aE10 = bBv.x, aE11 = bBv.y;
    ull aO00 = bAv.x, aO01 = bAv.y, aO10 = bBv.x, aO11 = bBv.y;

    const float* xp = smx + lane*sstr + u0*8;

    #pragma unroll 2
    for (int j = 0; j < jmax; ++j) {
        const ulonglong2* m = mbase + j*8;
        ulonglong2 m0 = m[0], m1 = m[1], m2 = m[2], m3 = m[3];
        ulonglong2 m4 = m[4], m5 = m[5], m6 = m[6], m7 = m[7];
        const float* xj = xp + j*8;
        float4 Xe = *reinterpret_cast<const float4*>(xj);
        float4 Xo = *reinterpret_cast<const float4*>(xj + 4);
        ull s;
        s = splat2(Xe.x);
        ffma2(aE00, s, m0.x); ffma2(aE01, s, m0.y);
        ffma2(aE10, s, m4.x); ffma2(aE11, s, m4.y);
        s = splat2(Xe.y);
        ffma2(aE00, s, m1.x); ffma2(aE01, s, m1.y);
        ffma2(aE10, s, m5.x); ffma2(aE11, s, m5.y);
        s = splat2(Xe.z);
        ffma2(aE00, s, m2.x); ffma2(aE01, s, m2.y);
        ffma2(aE10, s, m6.x); ffma2(aE11, s, m6.y);
        s = splat2(Xe.w);
        ffma2(aE00, s, m3.x); ffma2(aE01, s, m3.y);
        ffma2(aE10, s, m7.x); ffma2(aE11, s, m7.y);
        s = splat2(Xo.x);
        ffma2(aO00, s, m0.x); ffma2(aO01, s, m0.y);
        ffma2(aO10, s, m4.x); ffma2(aO11, s, m4.y);
        s = splat2(Xo.y);
        ffma2(aO00, s, m1.x); ffma2(aO01, s, m1.y);
        ffma2(aO10, s, m5.x); ffma2(aO11, s, m5.y);
        s = splat2(Xo.z);
        ffma2(aO00, s, m2.x); ffma2(aO01, s, m2.y);
        ffma2(aO10, s, m6.x); ffma2(aO11, s, m6.y);
        s = splat2(Xo.w);
        ffma2(aO00, s, m3.x); ffma2(aO01, s, m3.y);
        ffma2(aO10, s, m7.x); ffma2(aO11, s, m7.y);
    }

    __syncthreads();   // x tile dead; smo aliases smx

    // stage results: smo[row(64)][c2(4)*17 + fx(16)]
    {
        int rowl = 2*lane;
        float v0,v1,v2,v3;
        #pragma unroll
        for (int g = 0; g < 2; ++g) {
            int fx = 2*wrp + g;
            ull a0 = g ? aE10 : aE00, a1 = g ? aE11 : aE01;
            unpack2(a0, v0, v1); unpack2(a1, v2, v3);
            smo[rowl*69 + 0*17 + fx] = v0;
            smo[rowl*69 + 1*17 + fx] = v1;
            smo[rowl*69 + 2*17 + fx] = v2;
            smo[rowl*69 + 3*17 + fx] = v3;
            ull b0 = g ? aO10 : aO00, b1 = g ? aO11 : aO01;
            unpack2(b0, v0, v1); unpack2(b1, v2, v3);
            smo[(rowl+1)*69 + 0*17 + fx] = v0;
            smo[(rowl+1)*69 + 1*17 + fx] = v1;
            smo[(rowl+1)*69 + 2*17 + fx] = v2;
            smo[(rowl+1)*69 + 3*17 + fx] = v3;
        }
    }
    __syncthreads();

    // coalesced store: warp wrp covers rows 8*wrp..8*wrp+7
    #pragma unroll
    for (int rr = 0; rr < 8; ++rr) {
        const int r   = wrp*8 + rr;
        const int row = row0 + r, b = row >> 9, t = row & 511;
        #pragma unroll
        for (int h = 0; h < 2; ++h) {
            int e   = h*32 + lane;          // 0..63
            int fx  = e & 15, cc2 = e >> 4;
            int f = f0 + fx;
            if (f < Ff)
                out[((size_t)(b*4 + cc2)*512 + t)*Ff + f] = smo[r*69 + cc2*17 + fx];
        }
    }
}

// ---------------------------------------------------------------------------
extern "C" void kernel_launch(void* const* d_in, const int* in_sizes, int n_in,
                              void* d_out, int out_size)
{
    const float* x     = (const float*)d_in[0];
    const float* W1    = (const float*)d_in[1];
    const float* b1    = (const float*)d_in[2];
    const float* W2    = (const float*)d_in[3];
    const float* b2    = (const float*)d_in[4];
    const int*   nzidx = (const int*)  d_in[5];
    const float* nzmel = (const float*)d_in[6];
    const float* mask  = (const float*)d_in[7];
    const float* ola   = (const float*)d_in[8];

    const int Wb = in_sizes[5] / Kb;

    int gy = (4*Wb + 15) / 16;
    k_weff<<<dim3(Kb, gy), 256>>>(W1, b1, W2, b2, nzidx, nzmel, mask, ola, Wb);

    k_scatter<<<NFP, 256>>>(Wb);

    int xrange = 2*Wb + 16;
    int sstr = 8*xrange + 4;                     // floats per rowpair
    int main_smem = 32 * sstr * (int)sizeof(float);
    int smo_need = 64*69*(int)sizeof(float);
    if (main_smem < smo_need) main_smem = smo_need;
    cudaFuncSetAttribute(k_main, cudaFuncAttributeMaxDynamicSharedMemorySize, main_smem);
    k_main<<<dim3((Ff + 15)/16, NROWS/64), 256, main_smem>>>(x, (float*)d_out, sstr);
}